// round 5
// baseline (speedup 1.0000x reference)
#include <cuda_runtime.h>

// LSTM seq2seq: encoder (1->64) over T=1000, decoder (1->65) with teacher
// forcing over T=1000, output Linear(65->1). B=2048.
//
// Round 5: 512-thread CTAs, 2 CTAs/SM (32 warps/SM). Thread t=(pair,quarter)
// owns gate rows {2p,2p+1} x cols [16q,16q+16) -> only 32 weight regs, so
// two 512-thread CTAs fit the register file. Gate partials combined with a
// 3-shfl butterfly over the 4 quarters. h rows stored as 4 staggered 16-float
// segments (offsets 0/20/40/60, pitch 80) for conflict-free quarter-group
// LDS.128 broadcasts.

#define T_STEPS   1000
#define BATCH     2048
#define NCTA      296
#define NTHREADS  512
#define NWARPS    (NTHREADS / 32)
#define BT_MAX    7
#define HP        80     // h/c row pitch; h segs: cols [16q..16q+15] at q*20, col64 at 76
#define GP        264    // gates row pitch

typedef unsigned long long u64;

struct Smem {
    float h[BT_MAX * HP];   // staggered segment layout
    float c[BT_MAX * HP];   // linear (j = 0..64)
    float gates[BT_MAX * GP];
    float xbuf[2][BT_MAX];
    float xw[4 * 68];       // decoder extra gate rows 256..259 (65 weights, linear)
    float xwih[4];
    float xbias[4];
    float linW[68];         // linear
};

__device__ __forceinline__ u64 pack2(float lo, float hi) {
    u64 r;
    asm("mov.b64 %0, {%1, %2};" : "=l"(r) : "f"(lo), "f"(hi));
    return r;
}
__device__ __forceinline__ float2 unpack2(u64 v) {
    float lo, hi;
    asm("mov.b64 {%0, %1}, %2;" : "=f"(lo), "=f"(hi) : "l"(v));
    return make_float2(lo, hi);
}
__device__ __forceinline__ void ffma2(u64& d, u64 a, u64 b, u64 c) {
    asm("fma.rn.f32x2 %0, %1, %2, %3;" : "=l"(d) : "l"(a), "l"(b), "l"(c));
}

__device__ __forceinline__ float sigf(float x) {
    return __fdividef(1.0f, 1.0f + __expf(-x));
}
__device__ __forceinline__ float tanh_fast(float x) {
    float ax = fminf(fabsf(x), 15.0f);
    float e  = __expf(2.0f * ax);
    float t  = 1.0f - __fdividef(2.0f, e + 1.0f);
    return copysignf(t, x);
}

// h shared-layout offset for logical column j (0..64)
__device__ __forceinline__ int hoff(int j) {
    return (j < 64) ? ((j >> 4) * 20 + (j & 15)) : 76;
}

// Gate partials for NB batch rows. w2[0..7]=row r0 pairs, w2[8..15]=row r1
// pairs, covering this thread's 16-col quarter. Combine across quarters via
// shfl butterfly; quarter 0 stores row 2p, quarter 1 stores row 2p+1.
template <int H, int NB>
__device__ __forceinline__ void gate_block(
    Smem& sm, const float* xs, int b,
    const u64* w2, float wih_g, float bias_g, float wrem_g,
    int quarter, int row_store)
{
    u64 a0[NB], a1[NB];
    const ulonglong2* hp[NB];
#pragma unroll
    for (int u = 0; u < NB; u++) {
        a0[u] = 0ull;
        a1[u] = 0ull;
        hp[u] = (const ulonglong2*)(sm.h + (b + u) * HP + quarter * 20);
    }
#pragma unroll
    for (int k = 0; k < 4; k++) {
#pragma unroll
        for (int u = 0; u < NB; u++) {
            ulonglong2 h2 = hp[u][k];   // 4 disjoint-bank broadcast groups
            ffma2(a0[u], w2[2 * k],     h2.x, a0[u]);
            ffma2(a0[u], w2[2 * k + 1], h2.y, a0[u]);
            ffma2(a1[u], w2[8 + 2 * k], h2.x, a1[u]);
            ffma2(a1[u], w2[9 + 2 * k], h2.y, a1[u]);
        }
    }
#pragma unroll
    for (int u = 0; u < NB; u++) {
        float2 v0 = unpack2(a0[u]);
        float2 v1 = unpack2(a1[u]);
        float s0 = v0.x + v0.y;          // row r0 partial (this quarter)
        float s1 = v1.x + v1.y;          // row r1 partial
        s0 += __shfl_xor_sync(0xffffffffu, s0, 2);
        s1 += __shfl_xor_sync(0xffffffffu, s1, 2);
        const float send = (quarter & 1) ? s0 : s1;
        const float recv = __shfl_xor_sync(0xffffffffu, send, 1);
        const float fin  = ((quarter & 1) ? s1 : s0) + recv;
        if (quarter < 2) {
            float g = fmaf(wih_g, xs[b + u], bias_g + fin);
            if constexpr (H == 65)
                g = fmaf(wrem_g, sm.h[(b + u) * HP + 76], g);
            sm.gates[(b + u) * GP + row_store] = g;
        }
    }
}

template <int H, bool IS_DEC>
__device__ __forceinline__ void lstm_scan(
    Smem& sm, int bt, int b0,
    const float* __restrict__ xglob,
    const float* __restrict__ Wih,
    const float* __restrict__ Whh,
    const float* __restrict__ bih,
    const float* __restrict__ bhh,
    float* __restrict__ out,
    float linb)
{
    const int tid     = threadIdx.x;
    const int wid     = tid >> 5;
    const int lane    = tid & 31;
    const int quarter = tid & 3;
    const int pair    = tid >> 2;

    // ---- weight tile: rows {2p,2p+1}, cols [16q,16q+16) -> 16 u64 regs ----
    u64   w2[16];
    float wih_g, bias_g, wrem_g = 0.0f;
    {
        const int r0 = 2 * pair, r1 = r0 + 1;
        const float* wr0 = Whh + r0 * H + quarter * 16;
        const float* wr1 = Whh + r1 * H + quarter * 16;
#pragma unroll
        for (int k = 0; k < 8; k++) {
            w2[k]     = pack2(wr0[2 * k], wr0[2 * k + 1]);
            w2[8 + k] = pack2(wr1[2 * k], wr1[2 * k + 1]);
        }
        const int rs = 2 * pair + (quarter & 1);   // row this thread stores (if q<2)
        wih_g  = Wih[rs];
        bias_g = bih[rs] + bhh[rs];
        if constexpr (H == 65) wrem_g = Whh[rs * H + 64];
    }
    const int row_store = 2 * pair + (quarter & 1);

    // ---- pointwise-update mapping: <=1 element per thread ----
    const bool has_u = (tid < H * bt);
    int ub = 0, ujc = 0, ujh = 0;
    if (has_u) {
        ub  = tid / H;
        ujc = tid - ub * H;
        ujh = hoff(ujc);
    }

    for (int t = 0; t < T_STEPS; t++) {
        float xnext = 0.0f;
        const bool do_pref = (tid < bt) && (t + 1 < T_STEPS);
        if (do_pref) {
            const int row = IS_DEC ? t : (t + 1);
            xnext = xglob[row * BATCH + b0 + tid];
        }
        const float* xs = sm.xbuf[t & 1];

        // ---- gate phase ----
        {
            int b = 0;
            for (; b + 2 <= bt; b += 2)
                gate_block<H, 2>(sm, xs, b, w2, wih_g, bias_g, wrem_g, quarter, row_store);
            if (b < bt)
                gate_block<H, 1>(sm, xs, b, w2, wih_g, bias_g, wrem_g, quarter, row_store);
        }

        // ---- decoder: leftover gate rows 256..259, warp-cooperative ----
        if constexpr (IS_DEC) {
            const int ntask = 4 * bt;
            for (int task = wid; task < ntask; task += NWARPS) {
                const int e = task & 3;
                const int b = task >> 2;
                const float* w    = sm.xw + e * 68;
                const float* hrow = sm.h + b * HP;
                float p = w[lane]      * hrow[(lane >> 4) * 20 + (lane & 15)]
                        + w[lane + 32] * hrow[(2 + (lane >> 4)) * 20 + (lane & 15)];
                if (lane == 0) p += w[64] * hrow[76];
#pragma unroll
                for (int off = 16; off; off >>= 1)
                    p += __shfl_down_sync(0xffffffffu, p, off);
                if (lane == 0)
                    sm.gates[b * GP + 256 + e] =
                        sm.xbias[e] + sm.xwih[e] * xs[b] + p;
            }
        }

        if (do_pref) sm.xbuf[(t + 1) & 1][tid] = xnext;
        __syncthreads();

        // ---- pointwise LSTM update (1 element/thread) ----
        if (has_u) {
            const float* gr = sm.gates + ub * GP;
            const float gi = gr[ujc];
            const float gf = gr[H + ujc];
            const float gg = gr[2 * H + ujc];
            const float go = gr[3 * H + ujc];
            float c  = sm.c[ub * HP + ujc];
            float cn = sigf(gf) * c + sigf(gi) * tanh_fast(gg);
            sm.c[ub * HP + ujc] = cn;
            sm.h[ub * HP + ujh] = sigf(go) * tanh_fast(cn);
        }
        __syncthreads();

        // ---- decoder: output projection ----
        if constexpr (IS_DEC) {
            for (int b = wid; b < bt; b += NWARPS) {
                const float* hrow = sm.h + b * HP;
                float p = sm.linW[lane]      * hrow[(lane >> 4) * 20 + (lane & 15)]
                        + sm.linW[lane + 32] * hrow[(2 + (lane >> 4)) * 20 + (lane & 15)];
                if (lane == 0) p += sm.linW[64] * hrow[76];
#pragma unroll
                for (int off = 16; off; off >>= 1)
                    p += __shfl_down_sync(0xffffffffu, p, off);
                if (lane == 0)
                    out[t * BATCH + b0 + b] = p + linb;
            }
        }
    }
}

__global__ void __launch_bounds__(NTHREADS, 2)
lstm_seq2seq_kernel(
    const float* __restrict__ input,  const float* __restrict__ speed,
    const float* __restrict__ target,
    const float* __restrict__ eWih,   const float* __restrict__ eWhh,
    const float* __restrict__ ebih,   const float* __restrict__ ebhh,
    const float* __restrict__ dWih,   const float* __restrict__ dWhh,
    const float* __restrict__ dbih,   const float* __restrict__ dbhh,
    const float* __restrict__ linW,   const float* __restrict__ linb,
    const float* __restrict__ denseW, const float* __restrict__ denseb,
    float* __restrict__ out)
{
    __shared__ Smem sm;
    const int tid  = threadIdx.x;
    const int cta  = blockIdx.x;
    const int base = BATCH / NCTA;     // 6
    const int rem  = BATCH % NCTA;     // 272
    const int bt   = base + (cta < rem ? 1 : 0);
    const int b0   = cta * base + min(cta, rem);

    for (int i = tid; i < BT_MAX * HP; i += NTHREADS) {
        sm.h[i] = 0.0f;
        sm.c[i] = 0.0f;
    }
    for (int i = tid; i < 4 * 65; i += NTHREADS) {
        const int e = i / 65, k = i - e * 65;
        sm.xw[e * 68 + k] = dWhh[(256 + e) * 65 + k];
    }
    if (tid < 4) {
        sm.xwih[tid]  = dWih[256 + tid];
        sm.xbias[tid] = dbih[256 + tid] + dbhh[256 + tid];
    }
    for (int i = tid; i < 65; i += NTHREADS) sm.linW[i] = linW[i];
    if (tid < bt) sm.xbuf[0][tid] = input[b0 + tid];
    const float lb = linb[0];
    __syncthreads();

    // ---- encoder scan (H=64) ----
    lstm_scan<64, false>(sm, bt, b0, input, eWih, eWhh, ebih, ebhh, nullptr, 0.0f);

    // ---- transition: append Dense(speed) to hidden & cell, zero dec x0 ----
    if (tid < bt) {
        const float sp = denseb[0] + denseW[0] * speed[b0 + tid];
        sm.h[tid * HP + 76] = sp;      // h col 64 (staggered layout)
        sm.c[tid * HP + 64] = sp;      // c linear
        sm.xbuf[0][tid] = 0.0f;
    }
    __syncthreads();

    // ---- decoder scan (H=65) + output projection ----
    lstm_scan<65, true>(sm, bt, b0, target, dWih, dWhh, dbih, dbhh, out, lb);
}

extern "C" void kernel_launch(void* const* d_in, const int* in_sizes, int n_in,
                              void* d_out, int out_size)
{
    const float* input  = (const float*)d_in[0];
    const float* speed  = (const float*)d_in[1];
    const float* target = (const float*)d_in[2];
    const float* eWih   = (const float*)d_in[3];
    const float* eWhh   = (const float*)d_in[4];
    const float* ebih   = (const float*)d_in[5];
    const float* ebhh   = (const float*)d_in[6];
    const float* dWih   = (const float*)d_in[7];
    const float* dWhh   = (const float*)d_in[8];
    const float* dbih   = (const float*)d_in[9];
    const float* dbhh   = (const float*)d_in[10];
    const float* linW   = (const float*)d_in[11];
    const float* linb   = (const float*)d_in[12];
    const float* denseW = (const float*)d_in[13];
    const float* denseb = (const float*)d_in[14];
    float* out = (float*)d_out;

    lstm_seq2seq_kernel<<<NCTA, NTHREADS>>>(
        input, speed, target,
        eWih, eWhh, ebih, ebhh,
        dWih, dWhh, dbih, dbhh,
        linW, linb, denseW, denseb, out);
}

// round 6
// speedup vs baseline: 1.1882x; 1.1882x over previous
#include <cuda_runtime.h>

// LSTM seq2seq: encoder (1->64) over T=1000, decoder (1->65) with teacher
// forcing over T=1000, output Linear(65->1). B=2048.
//
// Round 6: 256 threads, 2 CTAs/SM (16 warps). Thread t=(Q=t>>2, s=t&3)
// owns gate rows [4Q,4Q+4) x cols [16s,16s+16): 64 weight floats in regs,
// each 16B h chunk feeds 8 FFMA2. Partials combined over the 4 k-slices
// with a 3-shfl butterfly; thread finalizes row 4Q + 2(s&1) + (s>>1).
// h rows stored as 4 staggered 16-float segments (offsets s*20, pitch 84,
// col64 at +80) for conflict-free slice-group LDS.128 broadcasts.

#define T_STEPS   1000
#define BATCH     2048
#define NCTA      296
#define NTHREADS  256
#define NWARPS    (NTHREADS / 32)
#define BT_MAX    7
#define HP        84     // h/c row pitch; h segs: cols [16s..16s+15] at s*20, col64 at 80
#define GP        264    // gates row pitch

typedef unsigned long long u64;

struct Smem {
    float h[BT_MAX * HP];   // staggered segment layout
    float c[BT_MAX * HP];   // linear (j = 0..64)
    float gates[BT_MAX * GP];
    float xbuf[2][BT_MAX];
    float xw[4 * 68];       // decoder extra gate rows 256..259 (65 weights, linear)
    float xwih[4];
    float xbias[4];
    float linW[68];         // linear
};

__device__ __forceinline__ u64 pack2(float lo, float hi) {
    u64 r;
    asm("mov.b64 %0, {%1, %2};" : "=l"(r) : "f"(lo), "f"(hi));
    return r;
}
__device__ __forceinline__ float2 unpack2(u64 v) {
    float lo, hi;
    asm("mov.b64 {%0, %1}, %2;" : "=f"(lo), "=f"(hi) : "l"(v));
    return make_float2(lo, hi);
}
__device__ __forceinline__ void ffma2(u64& d, u64 a, u64 b, u64 c) {
    asm("fma.rn.f32x2 %0, %1, %2, %3;" : "=l"(d) : "l"(a), "l"(b), "l"(c));
}

__device__ __forceinline__ float sigf(float x) {
    return __fdividef(1.0f, 1.0f + __expf(-x));
}
__device__ __forceinline__ float tanh_fast(float x) {
    float ax = fminf(fabsf(x), 15.0f);
    float e  = __expf(2.0f * ax);
    float t  = 1.0f - __fdividef(2.0f, e + 1.0f);
    return copysignf(t, x);
}

// h shared-layout offset for logical column j (0..64)
__device__ __forceinline__ int hoff(int j) {
    return (j < 64) ? ((j >> 4) * 20 + (j & 15)) : 80;
}

// Gate partials for NB batch rows. w2[r*8+j] = pair j of row 4Q+r on this
// thread's 16-col slice. 4 LDS.128 per batch row feed 32 FFMA2.
template <int H, int NB>
__device__ __forceinline__ void gate_block(
    Smem& sm, const float* xs, int b,
    const u64* w2, float wih_g, float bias_g, float wrem_g,
    int seg_off, int s, int row_g)
{
    u64 acc[NB][4];
    const ulonglong2* hp[NB];
#pragma unroll
    for (int u = 0; u < NB; u++) {
        acc[u][0] = acc[u][1] = acc[u][2] = acc[u][3] = 0ull;
        hp[u] = (const ulonglong2*)(sm.h + (b + u) * HP + seg_off);
    }
#pragma unroll
    for (int k = 0; k < 4; k++) {
#pragma unroll
        for (int u = 0; u < NB; u++) {
            ulonglong2 h2 = hp[u][k];   // 4 disjoint-bank broadcast groups
#pragma unroll
            for (int r = 0; r < 4; r++) {
                ffma2(acc[u][r], w2[r * 8 + 2 * k],     h2.x, acc[u][r]);
                ffma2(acc[u][r], w2[r * 8 + 2 * k + 1], h2.y, acc[u][r]);
            }
        }
    }
#pragma unroll
    for (int u = 0; u < NB; u++) {
        float2 v0 = unpack2(acc[u][0]);
        float2 v1 = unpack2(acc[u][1]);
        float2 v2 = unpack2(acc[u][2]);
        float2 v3 = unpack2(acc[u][3]);
        float p0 = v0.x + v0.y;
        float p1 = v1.x + v1.y;
        float p2 = v2.x + v2.y;
        float p3 = v3.x + v3.y;
        // step 1 (xor1): even s keeps rows {0,1}, odd keeps rows {2,3}
        const float sendA = (s & 1) ? p0 : p2;
        const float recvA = __shfl_xor_sync(0xffffffffu, sendA, 1);
        const float sendB = (s & 1) ? p1 : p3;
        const float recvB = __shfl_xor_sync(0xffffffffu, sendB, 1);
        const float a  = ((s & 1) ? p2 : p0) + recvA;
        const float bb = ((s & 1) ? p3 : p1) + recvB;
        // step 2 (xor2): keep one row fully summed
        const float sendC = (s & 2) ? a : bb;
        const float recvC = __shfl_xor_sync(0xffffffffu, sendC, 2);
        const float fin   = ((s & 2) ? bb : a) + recvC;
        float g = fmaf(wih_g, xs[b + u], bias_g + fin);
        if constexpr (H == 65)
            g = fmaf(wrem_g, sm.h[(b + u) * HP + 80], g);
        sm.gates[(b + u) * GP + row_g] = g;
    }
}

template <int H, bool IS_DEC>
__device__ __forceinline__ void lstm_scan(
    Smem& sm, int bt, int b0,
    const float* __restrict__ xglob,
    const float* __restrict__ Wih,
    const float* __restrict__ Whh,
    const float* __restrict__ bih,
    const float* __restrict__ bhh,
    float* __restrict__ out,
    float linb)
{
    const int tid  = threadIdx.x;
    const int wid  = tid >> 5;
    const int lane = tid & 31;
    const int s    = tid & 3;          // k-slice
    const int Q    = tid >> 2;         // row quad
    const int seg_off = s * 20;
    const int row_g   = 4 * Q + 2 * (s & 1) + (s >> 1);   // finalized row

    // ---- weight tile: rows [4Q,4Q+4), cols [16s,16s+16) -> 32 u64 regs ----
    u64   w2[32];
    float wih_g, bias_g, wrem_g = 0.0f;
    {
#pragma unroll
        for (int r = 0; r < 4; r++) {
            const float* wr = Whh + (4 * Q + r) * H + s * 16;
#pragma unroll
            for (int j = 0; j < 8; j++)
                w2[r * 8 + j] = pack2(wr[2 * j], wr[2 * j + 1]);
        }
        wih_g  = Wih[row_g];
        bias_g = bih[row_g] + bhh[row_g];
        if constexpr (H == 65) wrem_g = Whh[row_g * H + 64];
    }

    // ---- pointwise-update mapping: <=2 elements per thread ----
    int ucnt = 0;
    int ub[2], ujc[2], ujh[2];
    {
        const int npairs = H * bt;
        for (int p = tid; p < npairs; p += NTHREADS) {
            ub[ucnt]  = p / H;
            ujc[ucnt] = p - ub[ucnt] * H;
            ujh[ucnt] = hoff(ujc[ucnt]);
            ucnt++;
        }
    }

    for (int t = 0; t < T_STEPS; t++) {
        float xnext = 0.0f;
        const bool do_pref = (tid < bt) && (t + 1 < T_STEPS);
        if (do_pref) {
            const int row = IS_DEC ? t : (t + 1);
            xnext = xglob[row * BATCH + b0 + tid];
        }
        const float* xs = sm.xbuf[t & 1];

        // ---- gate phase ----
        {
            int b = 0;
            for (; b + 2 <= bt; b += 2)
                gate_block<H, 2>(sm, xs, b, w2, wih_g, bias_g, wrem_g, seg_off, s, row_g);
            if (b < bt)
                gate_block<H, 1>(sm, xs, b, w2, wih_g, bias_g, wrem_g, seg_off, s, row_g);
        }

        // ---- decoder: leftover gate rows 256..259, warp-cooperative ----
        if constexpr (IS_DEC) {
            const int ntask = 4 * bt;
            for (int task = wid; task < ntask; task += NWARPS) {
                const int e = task & 3;
                const int b = task >> 2;
                const float* w    = sm.xw + e * 68;
                const float* hrow = sm.h + b * HP;
                float p = w[lane]      * hrow[(lane >> 4) * 20 + (lane & 15)]
                        + w[lane + 32] * hrow[(2 + (lane >> 4)) * 20 + (lane & 15)];
                if (lane == 0) p += w[64] * hrow[80];
#pragma unroll
                for (int off = 16; off; off >>= 1)
                    p += __shfl_down_sync(0xffffffffu, p, off);
                if (lane == 0)
                    sm.gates[b * GP + 256 + e] =
                        sm.xbias[e] + sm.xwih[e] * xs[b] + p;
            }
        }

        if (do_pref) sm.xbuf[(t + 1) & 1][tid] = xnext;
        __syncthreads();

        // ---- pointwise LSTM update (<=2 elements/thread) ----
#pragma unroll
        for (int k = 0; k < 2; k++) {
            if (k < ucnt) {
                const int b = ub[k];
                const int j = ujc[k];
                const float* gr = sm.gates + b * GP;
                const float gi = gr[j];
                const float gf = gr[H + j];
                const float gg = gr[2 * H + j];
                const float go = gr[3 * H + j];
                float c  = sm.c[b * HP + j];
                float cn = sigf(gf) * c + sigf(gi) * tanh_fast(gg);
                sm.c[b * HP + j]      = cn;
                sm.h[b * HP + ujh[k]] = sigf(go) * tanh_fast(cn);
            }
        }
        __syncthreads();

        // ---- decoder: output projection ----
        if constexpr (IS_DEC) {
            for (int b = wid; b < bt; b += NWARPS) {
                const float* hrow = sm.h + b * HP;
                float p = sm.linW[lane]      * hrow[(lane >> 4) * 20 + (lane & 15)]
                        + sm.linW[lane + 32] * hrow[(2 + (lane >> 4)) * 20 + (lane & 15)];
                if (lane == 0) p += sm.linW[64] * hrow[80];
#pragma unroll
                for (int off = 16; off; off >>= 1)
                    p += __shfl_down_sync(0xffffffffu, p, off);
                if (lane == 0)
                    out[t * BATCH + b0 + b] = p + linb;
            }
        }
    }
}

__global__ void __launch_bounds__(NTHREADS, 2)
lstm_seq2seq_kernel(
    const float* __restrict__ input,  const float* __restrict__ speed,
    const float* __restrict__ target,
    const float* __restrict__ eWih,   const float* __restrict__ eWhh,
    const float* __restrict__ ebih,   const float* __restrict__ ebhh,
    const float* __restrict__ dWih,   const float* __restrict__ dWhh,
    const float* __restrict__ dbih,   const float* __restrict__ dbhh,
    const float* __restrict__ linW,   const float* __restrict__ linb,
    const float* __restrict__ denseW, const float* __restrict__ denseb,
    float* __restrict__ out)
{
    __shared__ Smem sm;
    const int tid  = threadIdx.x;
    const int cta  = blockIdx.x;
    const int base = BATCH / NCTA;     // 6
    const int rem  = BATCH % NCTA;     // 272
    const int bt   = base + (cta < rem ? 1 : 0);
    const int b0   = cta * base + min(cta, rem);

    for (int i = tid; i < BT_MAX * HP; i += NTHREADS) {
        sm.h[i] = 0.0f;
        sm.c[i] = 0.0f;
    }
    for (int i = tid; i < 4 * 65; i += NTHREADS) {
        const int e = i / 65, k = i - e * 65;
        sm.xw[e * 68 + k] = dWhh[(256 + e) * 65 + k];
    }
    if (tid < 4) {
        sm.xwih[tid]  = dWih[256 + tid];
        sm.xbias[tid] = dbih[256 + tid] + dbhh[256 + tid];
    }
    for (int i = tid; i < 65; i += NTHREADS) sm.linW[i] = linW[i];
    if (tid < bt) sm.xbuf[0][tid] = input[b0 + tid];
    const float lb = linb[0];
    __syncthreads();

    // ---- encoder scan (H=64) ----
    lstm_scan<64, false>(sm, bt, b0, input, eWih, eWhh, ebih, ebhh, nullptr, 0.0f);

    // ---- transition: append Dense(speed) to hidden & cell, zero dec x0 ----
    if (tid < bt) {
        const float sp = denseb[0] + denseW[0] * speed[b0 + tid];
        sm.h[tid * HP + 80] = sp;      // h col 64 (staggered layout)
        sm.c[tid * HP + 64] = sp;      // c linear
        sm.xbuf[0][tid] = 0.0f;
    }
    __syncthreads();

    // ---- decoder scan (H=65) + output projection ----
    lstm_scan<65, true>(sm, bt, b0, target, dWih, dWhh, dbih, dbhh, out, lb);
}

extern "C" void kernel_launch(void* const* d_in, const int* in_sizes, int n_in,
                              void* d_out, int out_size)
{
    const float* input  = (const float*)d_in[0];
    const float* speed  = (const float*)d_in[1];
    const float* target = (const float*)d_in[2];
    const float* eWih   = (const float*)d_in[3];
    const float* eWhh   = (const float*)d_in[4];
    const float* ebih   = (const float*)d_in[5];
    const float* ebhh   = (const float*)d_in[6];
    const float* dWih   = (const float*)d_in[7];
    const float* dWhh   = (const float*)d_in[8];
    const float* dbih   = (const float*)d_in[9];
    const float* dbhh   = (const float*)d_in[10];
    const float* linW   = (const float*)d_in[11];
    const float* linb   = (const float*)d_in[12];
    const float* denseW = (const float*)d_in[13];
    const float* denseb = (const float*)d_in[14];
    float* out = (float*)d_out;

    lstm_seq2seq_kernel<<<NCTA, NTHREADS>>>(
        input, speed, target,
        eWih, eWhh, ebih, ebhh,
        dWih, dWhh, dbih, dbhh,
        linW, linb, denseW, denseb, out);
}